// round 3
// baseline (speedup 1.0000x reference)
#include <cuda_runtime.h>
#include <cstdint>

#define B_DIM 32
#define S_LEN 2048
#define I_DIM 256
#define H_DIM 256

// ---------------------------------------------------------------------------
// helpers
// ---------------------------------------------------------------------------
__device__ __forceinline__ unsigned long long ffma2(unsigned long long a,
                                                    unsigned long long b,
                                                    unsigned long long c) {
    unsigned long long d;
    asm("fma.rn.f32x2 %0, %1, %2, %3;" : "=l"(d) : "l"(a), "l"(b), "l"(c));
    return d;
}
__device__ __forceinline__ unsigned long long pack2(float x, float y) {
    unsigned long long d;
    asm("mov.b64 %0, {%1, %2};" : "=l"(d) : "f"(x), "f"(y));
    return d;
}
__device__ __forceinline__ float2 unpack2(unsigned long long v) {
    float2 r;
    asm("mov.b64 {%0, %1}, %2;" : "=f"(r.x), "=f"(r.y) : "l"(v));
    return r;
}
__device__ __forceinline__ uint32_t smem_u32(const void* p) {
    uint32_t a;
    asm("{ .reg .u64 t; cvta.to.shared.u64 t, %1; cvt.u32.u64 %0, t; }"
        : "=r"(a) : "l"(p));
    return a;
}
__device__ __forceinline__ uint32_t mapa_u32(uint32_t a, uint32_t rank) {
    uint32_t d;
    asm("mapa.shared::cluster.u32 %0, %1, %2;" : "=r"(d) : "r"(a), "r"(rank));
    return d;
}
__device__ __forceinline__ void mbar_init(uint32_t mbar, uint32_t count) {
    asm volatile("mbarrier.init.shared.b64 [%0], %1;" :: "r"(mbar), "r"(count) : "memory");
}
__device__ __forceinline__ void mbar_arrive(uint32_t mbar) {
    asm volatile("mbarrier.arrive.shared.b64 _, [%0];" :: "r"(mbar) : "memory");
}
__device__ __forceinline__ void mbar_expect_tx(uint32_t mbar, uint32_t bytes) {
    asm volatile("mbarrier.arrive.expect_tx.shared.b64 _, [%0], %1;"
                 :: "r"(mbar), "r"(bytes) : "memory");
}
__device__ __forceinline__ void mbar_wait(uint32_t mbar, uint32_t parity) {
    asm volatile(
        "{\n\t.reg .pred P;\n\t"
        "WL%=:\n\t"
        "mbarrier.try_wait.parity.acquire.cta.shared::cta.b64 P, [%0], %1, 0x989680;\n\t"
        "@!P bra WL%=;\n\t}"
        :: "r"(mbar), "r"(parity) : "memory");
}
// single bulk smem->peer-smem copy; ONE complete_tx on the peer's mbarrier
__device__ __forceinline__ void bulk_to_peer(uint32_t dst_cluster, uint32_t src_cta,
                                             uint32_t bytes, uint32_t peer_mbar) {
    asm volatile("fence.proxy.async.shared::cta;" ::: "memory");
    asm volatile(
        "cp.async.bulk.shared::cluster.shared::cta.mbarrier::complete_tx::bytes "
        "[%0], [%1], %2, [%3];"
        :: "r"(dst_cluster), "r"(src_cta), "r"(bytes), "r"(peer_mbar) : "memory");
}
__device__ __forceinline__ float tanh_fast(float x) {
    float r;
    asm("tanh.approx.f32 %0, %1;" : "=f"(r) : "f"(x));
    return r;
}

// ---------------------------------------------------------------------------
// Kernel 1: xw[b,s,h] = x[b,s,:] . Wx_w[h,:] + Wx_b[h]  (into outputs region)
// ---------------------------------------------------------------------------
__global__ __launch_bounds__(256, 2)
void xw_gemm_kernel(const float* __restrict__ A, const float* __restrict__ W,
                    const float* __restrict__ bias, float* __restrict__ C) {
    __shared__ __align__(16) float As[16][128];
    __shared__ __align__(16) float Bs[16][128];

    const int tid = threadIdx.x;
    const int tx = tid & 15;
    const int ty = tid >> 4;
    const long bm = (long)blockIdx.x * 128;
    const long bn = (long)blockIdx.y * 128;

    const float* Ab = A + bm * I_DIM;
    const float* Wb = W + bn * I_DIM;

    unsigned long long acc[8][4];
#pragma unroll
    for (int i = 0; i < 8; i++)
#pragma unroll
        for (int j = 0; j < 4; j++) acc[i][j] = 0ull;

    for (int k0 = 0; k0 < I_DIM; k0 += 16) {
#pragma unroll
        for (int f = tid; f < 512; f += 256) {
            int row = f >> 2, kq = f & 3;
            float4 va = *(const float4*)(Ab + (long)row * I_DIM + k0 + kq * 4);
            As[kq * 4 + 0][row] = va.x; As[kq * 4 + 1][row] = va.y;
            As[kq * 4 + 2][row] = va.z; As[kq * 4 + 3][row] = va.w;
            float4 vw = *(const float4*)(Wb + (long)row * I_DIM + k0 + kq * 4);
            Bs[kq * 4 + 0][row] = vw.x; Bs[kq * 4 + 1][row] = vw.y;
            Bs[kq * 4 + 2][row] = vw.z; Bs[kq * 4 + 3][row] = vw.w;
        }
        __syncthreads();
#pragma unroll
        for (int k = 0; k < 16; k++) {
            const float4* As4 = (const float4*)&As[k][0];
            const ulonglong2* Bs2 = (const ulonglong2*)&Bs[k][0];
            float4 a0 = As4[ty * 2], a1 = As4[ty * 2 + 1];
            ulonglong2 bA = Bs2[tx * 2], bB = Bs2[tx * 2 + 1];
            unsigned long long bp[4] = {bA.x, bA.y, bB.x, bB.y};
            float av[8] = {a0.x, a0.y, a0.z, a0.w, a1.x, a1.y, a1.z, a1.w};
#pragma unroll
            for (int i = 0; i < 8; i++) {
                unsigned long long ap = pack2(av[i], av[i]);
#pragma unroll
                for (int j = 0; j < 4; j++) acc[i][j] = ffma2(ap, bp[j], acc[i][j]);
            }
        }
        __syncthreads();
    }

    float bv[8];
#pragma unroll
    for (int j = 0; j < 8; j++) bv[j] = bias[bn + tx * 8 + j];
#pragma unroll
    for (int i = 0; i < 8; i++) {
        long m = bm + ty * 8 + i;
        float* Crow = C + m * (long)H_DIM + bn + tx * 8;
        float2 c0 = unpack2(acc[i][0]), c1 = unpack2(acc[i][1]);
        float2 c2 = unpack2(acc[i][2]), c3 = unpack2(acc[i][3]);
        *(float4*)(Crow)     = make_float4(c0.x + bv[0], c0.y + bv[1], c1.x + bv[2], c1.y + bv[3]);
        *(float4*)(Crow + 4) = make_float4(c2.x + bv[4], c2.y + bv[5], c3.x + bv[6], c3.y + bv[7]);
    }
}

// ---------------------------------------------------------------------------
// Kernel 2: recurrence. 2-CTA cluster per batch row. Thread (jl,kc) holds 64
// Wh weights in regs (32 local-half k + 32 remote-half k). Per step:
//   local-half FMAs -> mbar wait (peer half) -> remote-half FMAs -> xor-shfl
//   reduce -> tanh.approx -> STS h -> __syncthreads -> ONE cp.async.bulk
//   ships the 512B h-half to the peer with a single complete_tx.
// ---------------------------------------------------------------------------
__global__ __launch_bounds__(512, 1) __cluster_dims__(2, 1, 1)
void srnn_recur_kernel(const float* __restrict__ Wh, float* __restrict__ out) {
    __shared__ __align__(16) float hL[2][128];   // my half (local writes, bulk src)
    __shared__ __align__(16) float hR[2][128];   // peer half (bulk dst)
    __shared__ __align__(8) unsigned long long mbar[2];

    const int rank = blockIdx.x;
    const int row  = blockIdx.y;
    const int t    = threadIdx.x;
    const int jl   = t >> 2;          // 0..127 local output index
    const int kc   = t & 3;           // 0..3 k-chunk (32 k per half each)
    const int jg   = rank * 128 + jl;

    // --- preload weights (stagger-rotated to match smem read pattern) ---
    unsigned long long wlA[8], wlB[8], wrA[8], wrB[8];
    {
        const float* wL = Wh + (long)jg * H_DIM + (rank * 128 + kc * 32);
        const float* wR = Wh + (long)jg * H_DIM + ((rank ^ 1) * 128 + kc * 32);
#pragma unroll
        for (int u = 0; u < 8; u++) {
            int slot = (u + 2 * kc) & 7;
            ulonglong2 a = *(const ulonglong2*)(wL + slot * 4);
            wlA[u] = a.x; wlB[u] = a.y;
            ulonglong2 b = *(const ulonglong2*)(wR + slot * 4);
            wrA[u] = b.x; wrB[u] = b.y;
        }
    }

    const uint32_t mb0 = smem_u32(&mbar[0]);
    const uint32_t mb1 = smem_u32(&mbar[1]);

    if (t == 0) {
        mbar_init(mb0, 1);
        mbar_init(mb1, 1);
        mbar_arrive(mb0);            // mbar[0] phase 0: trivially complete (h0 = 0)
        mbar_expect_tx(mb1, 512);    // armed for peer's step-0 bulk (targets hR[1])
    }
    if (t < 128) { hL[0][t] = 0.0f; hR[0][t] = 0.0f; }
    __syncthreads();
    asm volatile("barrier.cluster.arrive.aligned;" ::: "memory");
    asm volatile("barrier.cluster.wait.aligned;" ::: "memory");

    // peer-CTA destinations (my hL half lands in the peer's hR at same offset)
    const uint32_t dstR0 = mapa_u32(smem_u32(&hR[0][0]), rank ^ 1);
    const uint32_t dstR1 = mapa_u32(smem_u32(&hR[1][0]), rank ^ 1);
    const uint32_t srcL0 = smem_u32(&hL[0][0]);
    const uint32_t srcL1 = smem_u32(&hL[1][0]);
    const uint32_t pmb0  = mapa_u32(mb0, rank ^ 1);
    const uint32_t pmb1  = mapa_u32(mb1, rank ^ 1);

    float* xwp = out + (long)row * S_LEN * H_DIM + jg;
    float xw_next = xwp[0];                       // all lanes (broadcast)

    for (int step = 0; step < S_LEN; step++) {
        const int p = step & 1;
        float xw_cur = xw_next;
        if (step + 1 < S_LEN)
            xw_next = xwp[(long)(step + 1) * H_DIM];

        unsigned long long accA = 0ull, accB = 0ull;

        // ---- local half (hL[p] visible from last step's __syncthreads)
        {
            const ulonglong2* h2 = (const ulonglong2*)&hL[p][kc * 32];
#pragma unroll
            for (int u = 0; u < 8; u++) {
                int slot = (u + 2 * kc) & 7;
                ulonglong2 hv = h2[slot];
                accA = ffma2(hv.x, wlA[u], accA);
                accB = ffma2(hv.y, wlB[u], accB);
            }
        }

        // ---- wait for peer half, then re-arm this mbar for step+2
        const uint32_t mb = p ? mb1 : mb0;
        mbar_wait(mb, (step >> 1) & 1);
        if (t == 0) mbar_expect_tx(mb, 512);

        // ---- remote half
        {
            const ulonglong2* h2 = (const ulonglong2*)&hR[p][kc * 32];
#pragma unroll
            for (int u = 0; u < 8; u++) {
                int slot = (u + 2 * kc) & 7;
                ulonglong2 hv = h2[slot];
                accA = ffma2(hv.x, wrA[u], accA);
                accB = ffma2(hv.y, wrB[u], accB);
            }
        }

        float2 fA = unpack2(accA), fB = unpack2(accB);
        float s = (fA.x + fA.y) + (fB.x + fB.y);
        s += __shfl_xor_sync(0xffffffffu, s, 1);
        s += __shfl_xor_sync(0xffffffffu, s, 2);   // all 4 kc lanes hold full sum
        s += xw_cur;

        // spread the tail across kc lanes (redundant tanh, disjoint stores)
        if (kc == 0) {
            hL[p ^ 1][jl] = tanh_fast(s);
        } else if (kc == 1) {
            xwp[(long)step * H_DIM] = tanh_fast(s);          // in-place output
        } else if (kc == 2 && step == S_LEN - 1) {
            out[(long)B_DIM * S_LEN * H_DIM + (long)row * H_DIM + jg] = tanh_fast(s);
        }

        __syncthreads();  // hL[p^1] visible CTA-wide (and to the bulk engine)

        if (t == 511)     // one bulk copy, one complete_tx at the peer
            bulk_to_peer(p ? dstR0 : dstR1, p ? srcL0 : srcL1, 512,
                         p ? pmb0 : pmb1);
    }

    // keep smem alive until peer's in-flight bulk lands
    asm volatile("barrier.cluster.arrive.aligned;" ::: "memory");
    asm volatile("barrier.cluster.wait.aligned;" ::: "memory");
}

// ---------------------------------------------------------------------------
// Launch
// ---------------------------------------------------------------------------
extern "C" void kernel_launch(void* const* d_in, const int* in_sizes, int n_in,
                              void* d_out, int out_size) {
    const float* x    = (const float*)d_in[0];  // [B,S,I]
    const float* Wx_w = (const float*)d_in[1];  // [H,I]
    const float* Wx_b = (const float*)d_in[2];  // [H]
    const float* Wh_w = (const float*)d_in[3];  // [H,H]
    float* out = (float*)d_out;                 // [B,S,H] ++ [B,H]

    dim3 g1((B_DIM * S_LEN) / 128, H_DIM / 128);
    xw_gemm_kernel<<<g1, 256>>>(x, Wx_w, Wx_b, out);

    dim3 g2(2, B_DIM);
    srnn_recur_kernel<<<g2, 512>>>(Wh_w, out);
}

// round 4
// speedup vs baseline: 1.6137x; 1.6137x over previous
#include <cuda_runtime.h>
#include <cstdint>

#define B_DIM 32
#define S_LEN 2048
#define I_DIM 256
#define H_DIM 256

// ---------------------------------------------------------------------------
// helpers
// ---------------------------------------------------------------------------
__device__ __forceinline__ unsigned long long ffma2(unsigned long long a,
                                                    unsigned long long b,
                                                    unsigned long long c) {
    unsigned long long d;
    asm("fma.rn.f32x2 %0, %1, %2, %3;" : "=l"(d) : "l"(a), "l"(b), "l"(c));
    return d;
}
__device__ __forceinline__ unsigned long long pack2(float x, float y) {
    unsigned long long d;
    asm("mov.b64 %0, {%1, %2};" : "=l"(d) : "f"(x), "f"(y));
    return d;
}
__device__ __forceinline__ float2 unpack2(unsigned long long v) {
    float2 r;
    asm("mov.b64 {%0, %1}, %2;" : "=f"(r.x), "=f"(r.y) : "l"(v));
    return r;
}
__device__ __forceinline__ uint32_t smem_u32(const void* p) {
    uint32_t a;
    asm("{ .reg .u64 t; cvta.to.shared.u64 t, %1; cvt.u32.u64 %0, t; }"
        : "=r"(a) : "l"(p));
    return a;
}
__device__ __forceinline__ uint32_t mapa_u32(uint32_t a, uint32_t rank) {
    uint32_t d;
    asm("mapa.shared::cluster.u32 %0, %1, %2;" : "=r"(d) : "r"(a), "r"(rank));
    return d;
}
__device__ __forceinline__ void mbar_init(uint32_t mbar, uint32_t count) {
    asm volatile("mbarrier.init.shared.b64 [%0], %1;" :: "r"(mbar), "r"(count) : "memory");
}
__device__ __forceinline__ void mbar_arrive(uint32_t mbar) {
    asm volatile("mbarrier.arrive.shared.b64 _, [%0];" :: "r"(mbar) : "memory");
}
__device__ __forceinline__ void mbar_expect_tx(uint32_t mbar, uint32_t bytes) {
    asm volatile("mbarrier.arrive.expect_tx.shared.b64 _, [%0], %1;"
                 :: "r"(mbar), "r"(bytes) : "memory");
}
__device__ __forceinline__ void mbar_wait(uint32_t mbar, uint32_t parity) {
    asm volatile(
        "{\n\t.reg .pred P;\n\t"
        "WL%=:\n\t"
        "mbarrier.try_wait.parity.acquire.cta.shared::cta.b64 P, [%0], %1, 0x989680;\n\t"
        "@!P bra WL%=;\n\t}"
        :: "r"(mbar), "r"(parity) : "memory");
}
// 8-byte async store into peer CTA smem, auto-arriving 8 tx bytes on peer mbar
__device__ __forceinline__ void st_async_b64(uint32_t raddr, unsigned long long v,
                                             uint32_t rmbar) {
    asm volatile(
        "st.async.shared::cluster.mbarrier::complete_tx::bytes.b64 [%0], %1, [%2];"
        :: "r"(raddr), "l"(v), "r"(rmbar) : "memory");
}
__device__ __forceinline__ float tanh_fast(float x) {
    float r;
    asm("tanh.approx.f32 %0, %1;" : "=f"(r) : "f"(x));
    return r;
}

// ---------------------------------------------------------------------------
// Kernel 1: xw[b,s,h] = x[b,s,:] . Wx_w[h,:] + Wx_b[h]  (into outputs region)
// ---------------------------------------------------------------------------
__global__ __launch_bounds__(256, 2)
void xw_gemm_kernel(const float* __restrict__ A, const float* __restrict__ W,
                    const float* __restrict__ bias, float* __restrict__ C) {
    __shared__ __align__(16) float As[16][128];
    __shared__ __align__(16) float Bs[16][128];

    const int tid = threadIdx.x;
    const int tx = tid & 15;
    const int ty = tid >> 4;
    const long bm = (long)blockIdx.x * 128;
    const long bn = (long)blockIdx.y * 128;

    const float* Ab = A + bm * I_DIM;
    const float* Wb = W + bn * I_DIM;

    unsigned long long acc[8][4];
#pragma unroll
    for (int i = 0; i < 8; i++)
#pragma unroll
        for (int j = 0; j < 4; j++) acc[i][j] = 0ull;

    for (int k0 = 0; k0 < I_DIM; k0 += 16) {
#pragma unroll
        for (int f = tid; f < 512; f += 256) {
            int row = f >> 2, kq = f & 3;
            float4 va = *(const float4*)(Ab + (long)row * I_DIM + k0 + kq * 4);
            As[kq * 4 + 0][row] = va.x; As[kq * 4 + 1][row] = va.y;
            As[kq * 4 + 2][row] = va.z; As[kq * 4 + 3][row] = va.w;
            float4 vw = *(const float4*)(Wb + (long)row * I_DIM + k0 + kq * 4);
            Bs[kq * 4 + 0][row] = vw.x; Bs[kq * 4 + 1][row] = vw.y;
            Bs[kq * 4 + 2][row] = vw.z; Bs[kq * 4 + 3][row] = vw.w;
        }
        __syncthreads();
#pragma unroll
        for (int k = 0; k < 16; k++) {
            const float4* As4 = (const float4*)&As[k][0];
            const ulonglong2* Bs2 = (const ulonglong2*)&Bs[k][0];
            float4 a0 = As4[ty * 2], a1 = As4[ty * 2 + 1];
            ulonglong2 bA = Bs2[tx * 2], bB = Bs2[tx * 2 + 1];
            unsigned long long bp[4] = {bA.x, bA.y, bB.x, bB.y};
            float av[8] = {a0.x, a0.y, a0.z, a0.w, a1.x, a1.y, a1.z, a1.w};
#pragma unroll
            for (int i = 0; i < 8; i++) {
                unsigned long long ap = pack2(av[i], av[i]);
#pragma unroll
                for (int j = 0; j < 4; j++) acc[i][j] = ffma2(ap, bp[j], acc[i][j]);
            }
        }
        __syncthreads();
    }

    float bv[8];
#pragma unroll
    for (int j = 0; j < 8; j++) bv[j] = bias[bn + tx * 8 + j];
#pragma unroll
    for (int i = 0; i < 8; i++) {
        long m = bm + ty * 8 + i;
        float* Crow = C + m * (long)H_DIM + bn + tx * 8;
        float2 c0 = unpack2(acc[i][0]), c1 = unpack2(acc[i][1]);
        float2 c2 = unpack2(acc[i][2]), c3 = unpack2(acc[i][3]);
        *(float4*)(Crow)     = make_float4(c0.x + bv[0], c0.y + bv[1], c1.x + bv[2], c1.y + bv[3]);
        *(float4*)(Crow + 4) = make_float4(c2.x + bv[4], c2.y + bv[5], c3.x + bv[6], c3.y + bv[7]);
    }
}

// ---------------------------------------------------------------------------
// Kernel 2: recurrence. 2-CTA cluster per batch row. Thread (jl,kc) holds 64
// Wh weights in regs (32 local-half k + 32 remote-half k). Per step:
//   local-half FMAs -> mbar wait (peer half) -> remote-half FMAs -> xor-shfl
//   reduce -> tanh (all lanes) -> pack j-pairs -> 64x st.async.b64 to peer
//   (single complete_tx each), tail stores spread across kc lanes.
// ---------------------------------------------------------------------------
__global__ __launch_bounds__(512, 1) __cluster_dims__(2, 1, 1)
void srnn_recur_kernel(const float* __restrict__ Wh, float* __restrict__ out) {
    __shared__ __align__(16) float hL[2][128];   // my half (local writes)
    __shared__ __align__(16) float hR[2][128];   // peer half (st.async dst)
    __shared__ __align__(8) unsigned long long mbar[2];

    const int rank = blockIdx.x;
    const int row  = blockIdx.y;
    const int t    = threadIdx.x;
    const int jl   = t >> 2;          // 0..127 local output index
    const int kc   = t & 3;           // 0..3 k-chunk (32 k per half each)
    const int jg   = rank * 128 + jl;

    // --- preload weights (stagger-rotated to match smem read pattern) ---
    unsigned long long wlA[8], wlB[8], wrA[8], wrB[8];
    {
        const float* wL = Wh + (long)jg * H_DIM + (rank * 128 + kc * 32);
        const float* wR = Wh + (long)jg * H_DIM + ((rank ^ 1) * 128 + kc * 32);
#pragma unroll
        for (int u = 0; u < 8; u++) {
            int slot = (u + 2 * kc) & 7;
            ulonglong2 a = *(const ulonglong2*)(wL + slot * 4);
            wlA[u] = a.x; wlB[u] = a.y;
            ulonglong2 b = *(const ulonglong2*)(wR + slot * 4);
            wrA[u] = b.x; wrB[u] = b.y;
        }
    }

    const uint32_t mb0 = smem_u32(&mbar[0]);
    const uint32_t mb1 = smem_u32(&mbar[1]);

    if (t == 0) {
        mbar_init(mb0, 1);
        mbar_init(mb1, 1);
        mbar_arrive(mb0);            // mbar[0] phase 0: trivially complete (h0 = 0)
        mbar_expect_tx(mb1, 512);    // armed for peer's step-0 sends (-> hR[1])
    }
    if (t < 128) { hL[0][t] = 0.0f; hR[0][t] = 0.0f; }
    __syncthreads();
    asm volatile("barrier.cluster.arrive.aligned;" ::: "memory");
    asm volatile("barrier.cluster.wait.aligned;" ::: "memory");

    // peer-CTA base addresses of hR buffers + peer mbars
    const uint32_t prB0 = mapa_u32(smem_u32(&hR[0][0]), rank ^ 1);
    const uint32_t prB1 = mapa_u32(smem_u32(&hR[1][0]), rank ^ 1);
    const uint32_t pmb0 = mapa_u32(mb0, rank ^ 1);
    const uint32_t pmb1 = mapa_u32(mb1, rank ^ 1);

    // this lane ships the pair {jl, jl+1} iff kc==2 and jl even
    const bool shipper = (kc == 2) && ((jl & 1) == 0);
    const uint32_t shipoff = (uint32_t)jl * 4u;

    float* xwp = out + (long)row * S_LEN * H_DIM + jg;
    float xw_next = xwp[0];                      // broadcast across kc lanes

    for (int step = 0; step < S_LEN; step++) {
        const int p = step & 1;
        float xw_cur = xw_next;
        if (step + 1 < S_LEN)
            xw_next = xwp[(long)(step + 1) * H_DIM];

        unsigned long long accA = 0ull, accB = 0ull;

        // ---- local half (hL[p] visible from last step's __syncthreads)
        {
            const ulonglong2* h2 = (const ulonglong2*)&hL[p][kc * 32];
#pragma unroll
            for (int u = 0; u < 8; u++) {
                int slot = (u + 2 * kc) & 7;
                ulonglong2 hv = h2[slot];
                accA = ffma2(hv.x, wlA[u], accA);
                accB = ffma2(hv.y, wlB[u], accB);
            }
        }

        // ---- wait for peer half, then re-arm this mbar for step+2
        const uint32_t mb = p ? mb1 : mb0;
        mbar_wait(mb, (step >> 1) & 1);
        if (t == 3) mbar_expect_tx(mb, 512);

        // ---- remote half
        {
            const ulonglong2* h2 = (const ulonglong2*)&hR[p][kc * 32];
#pragma unroll
            for (int u = 0; u < 8; u++) {
                int slot = (u + 2 * kc) & 7;
                ulonglong2 hv = h2[slot];
                accA = ffma2(hv.x, wrA[u], accA);
                accB = ffma2(hv.y, wrB[u], accB);
            }
        }

        float2 fA = unpack2(accA), fB = unpack2(accB);
        float s = (fA.x + fA.y) + (fB.x + fB.y);
        s += __shfl_xor_sync(0xffffffffu, s, 1);
        s += __shfl_xor_sync(0xffffffffu, s, 2);   // all 4 kc lanes: full sum

        float v   = tanh_fast(s + xw_cur);                  // all lanes
        float vhi = __shfl_down_sync(0xffffffffu, v, 4);    // jl+1's value

        if (shipper) {          // 64 b64 messages/step (kc2 lanes, even jl)
            st_async_b64((p ? prB0 : prB1) + shipoff, pack2(v, vhi),
                         p ? pmb0 : pmb1);
        } else if (kc == 0) {
            hL[p ^ 1][jl] = v;                              // local half STS
        } else if (kc == 1) {
            xwp[(long)step * H_DIM] = v;                    // in-place output
        } else if (kc == 3 && step == S_LEN - 1) {
            out[(long)B_DIM * S_LEN * H_DIM + (long)row * H_DIM + jg] = v;
        }

        __syncthreads();  // hL[p^1] visible CTA-wide before next step
    }

    // keep smem alive until peer's in-flight st.asyncs land
    asm volatile("barrier.cluster.arrive.aligned;" ::: "memory");
    asm volatile("barrier.cluster.wait.aligned;" ::: "memory");
}

// ---------------------------------------------------------------------------
// Launch
// ---------------------------------------------------------------------------
extern "C" void kernel_launch(void* const* d_in, const int* in_sizes, int n_in,
                              void* d_out, int out_size) {
    const float* x    = (const float*)d_in[0];  // [B,S,I]
    const float* Wx_w = (const float*)d_in[1];  // [H,I]
    const float* Wx_b = (const float*)d_in[2];  // [H]
    const float* Wh_w = (const float*)d_in[3];  // [H,H]
    float* out = (float*)d_out;                 // [B,S,H] ++ [B,H]

    dim3 g1((B_DIM * S_LEN) / 128, H_DIM / 128);
    xw_gemm_kernel<<<g1, 256>>>(x, Wx_w, Wx_b, out);

    dim3 g2(2, B_DIM);
    srnn_recur_kernel<<<g2, 512>>>(Wh_w, out);
}

// round 5
// speedup vs baseline: 1.6487x; 1.0217x over previous
#include <cuda_runtime.h>
#include <cstdint>

#define B_DIM 32
#define S_LEN 2048
#define I_DIM 256
#define H_DIM 256

// ---------------------------------------------------------------------------
// helpers
// ---------------------------------------------------------------------------
__device__ __forceinline__ unsigned long long ffma2(unsigned long long a,
                                                    unsigned long long b,
                                                    unsigned long long c) {
    unsigned long long d;
    asm("fma.rn.f32x2 %0, %1, %2, %3;" : "=l"(d) : "l"(a), "l"(b), "l"(c));
    return d;
}
__device__ __forceinline__ unsigned long long pack2(float x, float y) {
    unsigned long long d;
    asm("mov.b64 %0, {%1, %2};" : "=l"(d) : "f"(x), "f"(y));
    return d;
}
__device__ __forceinline__ float2 unpack2(unsigned long long v) {
    float2 r;
    asm("mov.b64 {%0, %1}, %2;" : "=f"(r.x), "=f"(r.y) : "l"(v));
    return r;
}
__device__ __forceinline__ uint32_t smem_u32(const void* p) {
    uint32_t a;
    asm("{ .reg .u64 t; cvta.to.shared.u64 t, %1; cvt.u32.u64 %0, t; }"
        : "=r"(a) : "l"(p));
    return a;
}
__device__ __forceinline__ uint32_t mapa_u32(uint32_t a, uint32_t rank) {
    uint32_t d;
    asm("mapa.shared::cluster.u32 %0, %1, %2;" : "=r"(d) : "r"(a), "r"(rank));
    return d;
}
__device__ __forceinline__ void mbar_init(uint32_t mbar, uint32_t count) {
    asm volatile("mbarrier.init.shared.b64 [%0], %1;" :: "r"(mbar), "r"(count) : "memory");
}
__device__ __forceinline__ void mbar_arrive(uint32_t mbar) {
    asm volatile("mbarrier.arrive.shared.b64 _, [%0];" :: "r"(mbar) : "memory");
}
__device__ __forceinline__ void mbar_expect_tx(uint32_t mbar, uint32_t bytes) {
    asm volatile("mbarrier.arrive.expect_tx.shared.b64 _, [%0], %1;"
                 :: "r"(mbar), "r"(bytes) : "memory");
}
__device__ __forceinline__ void mbar_wait(uint32_t mbar, uint32_t parity) {
    asm volatile(
        "{\n\t.reg .pred P;\n\t"
        "WL%=:\n\t"
        "mbarrier.try_wait.parity.acquire.cta.shared::cta.b64 P, [%0], %1, 0x989680;\n\t"
        "@!P bra WL%=;\n\t}"
        :: "r"(mbar), "r"(parity) : "memory");
}
__device__ __forceinline__ void st_async_b64(uint32_t raddr, unsigned long long v,
                                             uint32_t rmbar) {
    asm volatile(
        "st.async.shared::cluster.mbarrier::complete_tx::bytes.b64 [%0], %1, [%2];"
        :: "r"(raddr), "l"(v), "r"(rmbar) : "memory");
}
__device__ __forceinline__ float tanh_fast(float x) {
    float r;
    asm("tanh.approx.f32 %0, %1;" : "=f"(r) : "f"(x));
    return r;
}

// ---------------------------------------------------------------------------
// Kernel 1: xw[b,s,h] = x[b,s,:] . Wx_w[h,:] + Wx_b[h]  (into outputs region)
// ---------------------------------------------------------------------------
__global__ __launch_bounds__(256, 2)
void xw_gemm_kernel(const float* __restrict__ A, const float* __restrict__ W,
                    const float* __restrict__ bias, float* __restrict__ C) {
    __shared__ __align__(16) float As[16][128];
    __shared__ __align__(16) float Bs[16][128];

    const int tid = threadIdx.x;
    const int tx = tid & 15;
    const int ty = tid >> 4;
    const long bm = (long)blockIdx.x * 128;
    const long bn = (long)blockIdx.y * 128;

    const float* Ab = A + bm * I_DIM;
    const float* Wb = W + bn * I_DIM;

    unsigned long long acc[8][4];
#pragma unroll
    for (int i = 0; i < 8; i++)
#pragma unroll
        for (int j = 0; j < 4; j++) acc[i][j] = 0ull;

    for (int k0 = 0; k0 < I_DIM; k0 += 16) {
#pragma unroll
        for (int f = tid; f < 512; f += 256) {
            int row = f >> 2, kq = f & 3;
            float4 va = *(const float4*)(Ab + (long)row * I_DIM + k0 + kq * 4);
            As[kq * 4 + 0][row] = va.x; As[kq * 4 + 1][row] = va.y;
            As[kq * 4 + 2][row] = va.z; As[kq * 4 + 3][row] = va.w;
            float4 vw = *(const float4*)(Wb + (long)row * I_DIM + k0 + kq * 4);
            Bs[kq * 4 + 0][row] = vw.x; Bs[kq * 4 + 1][row] = vw.y;
            Bs[kq * 4 + 2][row] = vw.z; Bs[kq * 4 + 3][row] = vw.w;
        }
        __syncthreads();
#pragma unroll
        for (int k = 0; k < 16; k++) {
            const float4* As4 = (const float4*)&As[k][0];
            const ulonglong2* Bs2 = (const ulonglong2*)&Bs[k][0];
            float4 a0 = As4[ty * 2], a1 = As4[ty * 2 + 1];
            ulonglong2 bA = Bs2[tx * 2], bB = Bs2[tx * 2 + 1];
            unsigned long long bp[4] = {bA.x, bA.y, bB.x, bB.y};
            float av[8] = {a0.x, a0.y, a0.z, a0.w, a1.x, a1.y, a1.z, a1.w};
#pragma unroll
            for (int i = 0; i < 8; i++) {
                unsigned long long ap = pack2(av[i], av[i]);
#pragma unroll
                for (int j = 0; j < 4; j++) acc[i][j] = ffma2(ap, bp[j], acc[i][j]);
            }
        }
        __syncthreads();
    }

    float bv[8];
#pragma unroll
    for (int j = 0; j < 8; j++) bv[j] = bias[bn + tx * 8 + j];
#pragma unroll
    for (int i = 0; i < 8; i++) {
        long m = bm + ty * 8 + i;
        float* Crow = C + m * (long)H_DIM + bn + tx * 8;
        float2 c0 = unpack2(acc[i][0]), c1 = unpack2(acc[i][1]);
        float2 c2 = unpack2(acc[i][2]), c3 = unpack2(acc[i][3]);
        *(float4*)(Crow)     = make_float4(c0.x + bv[0], c0.y + bv[1], c1.x + bv[2], c1.y + bv[3]);
        *(float4*)(Crow + 4) = make_float4(c2.x + bv[4], c2.y + bv[5], c3.x + bv[6], c3.y + bv[7]);
    }
}

// ---------------------------------------------------------------------------
// Kernel 2: recurrence. 2-CTA cluster per batch row, 256 threads (8 warps).
// Thread (jl 0..127, kc 0..1) holds 128 Wh weights in regs: 64 local-half k
// + 64 remote-half k. Per step: local FMAs -> mbar wait -> remote FMAs ->
// 1 xor-shfl reduce -> tanh -> kc0 STS+STG, kc1-even ships j-pairs to peer.
// ---------------------------------------------------------------------------
__global__ __launch_bounds__(256, 1) __cluster_dims__(2, 1, 1)
void srnn_recur_kernel(const float* __restrict__ Wh, float* __restrict__ out) {
    __shared__ __align__(16) float hL[2][128];   // my half (local STS)
    __shared__ __align__(16) float hR[2][128];   // peer half (st.async dst)
    __shared__ __align__(8) unsigned long long mbar[2];

    const int rank = blockIdx.x;
    const int row  = blockIdx.y;
    const int t    = threadIdx.x;
    const int jl   = t >> 1;          // 0..127 local output index
    const int kc   = t & 1;           // 0..1 k-chunk (64 k per half each)
    const int jg   = rank * 128 + jl;

    // --- preload 128 weights: 64 local-half + 64 remote-half ---
    unsigned long long wlA[16], wlB[16], wrA[16], wrB[16];
    {
        const float* wL = Wh + (long)jg * H_DIM + (rank * 128 + kc * 64);
        const float* wR = Wh + (long)jg * H_DIM + ((rank ^ 1) * 128 + kc * 64);
#pragma unroll
        for (int u = 0; u < 16; u++) {
            ulonglong2 a = *(const ulonglong2*)(wL + u * 4);
            wlA[u] = a.x; wlB[u] = a.y;
            ulonglong2 b = *(const ulonglong2*)(wR + u * 4);
            wrA[u] = b.x; wrB[u] = b.y;
        }
    }

    const uint32_t mb0 = smem_u32(&mbar[0]);
    const uint32_t mb1 = smem_u32(&mbar[1]);

    if (t == 0) {
        mbar_init(mb0, 1);
        mbar_init(mb1, 1);
        mbar_arrive(mb0);            // mbar[0] phase 0: trivially complete (h0 = 0)
        mbar_expect_tx(mb1, 512);    // armed for peer's step-0 sends (-> hR[1])
    }
    if (t < 128) { hL[0][t] = 0.0f; hR[0][t] = 0.0f; }
    __syncthreads();
    asm volatile("barrier.cluster.arrive.aligned;" ::: "memory");
    asm volatile("barrier.cluster.wait.aligned;" ::: "memory");

    const uint32_t prB0 = mapa_u32(smem_u32(&hR[0][0]), rank ^ 1);
    const uint32_t prB1 = mapa_u32(smem_u32(&hR[1][0]), rank ^ 1);
    const uint32_t pmb0 = mapa_u32(mb0, rank ^ 1);
    const uint32_t pmb1 = mapa_u32(mb1, rank ^ 1);

    // kc==1 lanes with even jl ship the pair {v_jl, v_jl+1}
    const bool shipper = (kc == 1) && ((jl & 1) == 0);
    const uint32_t shipoff = (uint32_t)jl * 4u;

    float* xwp = out + (long)row * S_LEN * H_DIM + jg;
    float xw_next = xwp[0];

    for (int step = 0; step < S_LEN; step++) {
        const int p = step & 1;
        float xw_cur = xw_next;
        if (step + 1 < S_LEN)
            xw_next = xwp[(long)(step + 1) * H_DIM];

        unsigned long long a0 = 0ull, a1 = 0ull, a2 = 0ull, a3 = 0ull;

        // ---- local half (hL[p] visible from last step's __syncthreads)
        {
            const ulonglong2* h2 = (const ulonglong2*)&hL[p][kc * 64];
#pragma unroll
            for (int u = 0; u < 16; u += 2) {
                ulonglong2 h0 = h2[u], h1 = h2[u + 1];
                a0 = ffma2(h0.x, wlA[u], a0);
                a1 = ffma2(h0.y, wlB[u], a1);
                a2 = ffma2(h1.x, wlA[u + 1], a2);
                a3 = ffma2(h1.y, wlB[u + 1], a3);
            }
        }

        // ---- wait for peer half, then re-arm this mbar for step+2
        const uint32_t mb = p ? mb1 : mb0;
        mbar_wait(mb, (step >> 1) & 1);
        if (t == 3) mbar_expect_tx(mb, 512);

        // ---- remote half
        {
            const ulonglong2* h2 = (const ulonglong2*)&hR[p][kc * 64];
#pragma unroll
            for (int u = 0; u < 16; u += 2) {
                ulonglong2 h0 = h2[u], h1 = h2[u + 1];
                a0 = ffma2(h0.x, wrA[u], a0);
                a1 = ffma2(h0.y, wrB[u], a1);
                a2 = ffma2(h1.x, wrA[u + 1], a2);
                a3 = ffma2(h1.y, wrB[u + 1], a3);
            }
        }

        float2 f0 = unpack2(a0), f1 = unpack2(a1);
        float2 f2 = unpack2(a2), f3 = unpack2(a3);
        float s = ((f0.x + f0.y) + (f1.x + f1.y)) +
                  ((f2.x + f2.y) + (f3.x + f3.y));
        s += __shfl_xor_sync(0xffffffffu, s, 1);   // both kc lanes: full sum

        float v   = tanh_fast(s + xw_cur);
        float vhi = __shfl_down_sync(0xffffffffu, v, 2);   // jl+1's value

        if (shipper) {
            st_async_b64((p ? prB0 : prB1) + shipoff, pack2(v, vhi),
                         p ? pmb0 : pmb1);
        } else if (kc == 0) {
            hL[p ^ 1][jl] = v;                    // local half STS
            xwp[(long)step * H_DIM] = v;          // in-place output
        }
        if (kc == 1 && step == S_LEN - 1)
            out[(long)B_DIM * S_LEN * H_DIM + (long)row * H_DIM + jg] = v;

        __syncthreads();
    }

    asm volatile("barrier.cluster.arrive.aligned;" ::: "memory");
    asm volatile("barrier.cluster.wait.aligned;" ::: "memory");
}

// ---------------------------------------------------------------------------
// Launch
// ---------------------------------------------------------------------------
extern "C" void kernel_launch(void* const* d_in, const int* in_sizes, int n_in,
                              void* d_out, int out_size) {
    const float* x    = (const float*)d_in[0];  // [B,S,I]
    const float* Wx_w = (const float*)d_in[1];  // [H,I]
    const float* Wx_b = (const float*)d_in[2];  // [H]
    const float* Wh_w = (const float*)d_in[3];  // [H,H]
    float* out = (float*)d_out;                 // [B,S,H] ++ [B,H]

    dim3 g1((B_DIM * S_LEN) / 128, H_DIM / 128);
    xw_gemm_kernel<<<g1, 256>>>(x, Wx_w, Wx_b, out);

    dim3 g2(2, B_DIM);
    srnn_recur_kernel<<<g2, 256>>>(Wh_w, out);
}